// round 5
// baseline (speedup 1.0000x reference)
#include <cuda_runtime.h>
#include <math.h>
#include <stdint.h>

#define S_LEN 2048
#define B_SZ  64
#define E_SZ  256
#define H_SZ  256

// Scratch for x_proj: [S, B, H] fp32 = 134 MB
__device__ float g_xproj[(size_t)S_LEN * B_SZ * H_SZ];

typedef unsigned long long ull;

// ---- packed f32x2 helpers (Blackwell sm_103a) -------------------------------
__device__ __forceinline__ ull fma2(ull a, ull b, ull c) {
    ull d;
    asm("fma.rn.f32x2 %0, %1, %2, %3;" : "=l"(d) : "l"(a), "l"(b), "l"(c));
    return d;
}
__device__ __forceinline__ ull add2(ull a, ull b) {
    ull d;
    asm("add.rn.f32x2 %0, %1, %2;" : "=l"(d) : "l"(a), "l"(b));
    return d;
}
__device__ __forceinline__ ull pack2(float lo, float hi) {
    ull d;
    asm("mov.b64 %0, {%1, %2};" : "=l"(d) : "f"(lo), "f"(hi));
    return d;
}
__device__ __forceinline__ void unpack2(ull v, float& lo, float& hi) {
    asm("mov.b64 {%0, %1}, %2;" : "=f"(lo), "=f"(hi) : "l"(v));
}

// ---- cluster / mbarrier helpers --------------------------------------------
__device__ __forceinline__ uint32_t smem_u32(const void* p) {
    uint32_t a;
    asm("{ .reg .u64 t; cvta.to.shared.u64 t, %1; cvt.u32.u64 %0, t; }"
        : "=r"(a) : "l"(p));
    return a;
}
__device__ __forceinline__ uint32_t ctarank() {
    uint32_t r;
    asm("mov.u32 %0, %%cluster_ctarank;" : "=r"(r));
    return r;
}
__device__ __forceinline__ uint32_t mapa_cluster(uint32_t addr, uint32_t rank) {
    uint32_t r;
    asm("mapa.shared::cluster.u32 %0, %1, %2;" : "=r"(r) : "r"(addr), "r"(rank));
    return r;
}
__device__ __forceinline__ void st_async64(uint32_t raddr, ull v, uint32_t rmbar) {
    asm volatile(
        "st.async.shared::cluster.mbarrier::complete_tx::bytes.b64 [%0], %1, [%2];"
        :: "r"(raddr), "l"(v), "r"(rmbar) : "memory");
}
__device__ __forceinline__ void mbar_init(uint32_t mbar, uint32_t count) {
    asm volatile("mbarrier.init.shared.b64 [%0], %1;"
                 :: "r"(mbar), "r"(count) : "memory");
}
__device__ __forceinline__ void mbar_arrive_expect_tx(uint32_t mbar, uint32_t bytes) {
    asm volatile("mbarrier.arrive.expect_tx.shared.b64 _, [%0], %1;"
                 :: "r"(mbar), "r"(bytes) : "memory");
}
__device__ __forceinline__ void mbar_wait_parity_cluster(uint32_t mbar, uint32_t parity) {
    uint32_t done;
    asm volatile(
        "{\n\t"
        ".reg .pred p;\n\t"
        "mbarrier.try_wait.parity.acquire.cluster.shared::cta.b64 p, [%1], %2;\n\t"
        "selp.b32 %0, 1, 0, p;\n\t"
        "}"
        : "=r"(done) : "r"(mbar), "r"(parity) : "memory");
    if (!done) {
        asm volatile(
            "{\n\t"
            ".reg .pred P1;\n\t"
            "WAIT_LOOP_%=:\n\t"
            "mbarrier.try_wait.parity.acquire.cluster.shared::cta.b64 P1, [%0], %1, 0x989680;\n\t"
            "@P1 bra.uni WAIT_DONE_%=;\n\t"
            "bra.uni WAIT_LOOP_%=;\n\t"
            "WAIT_DONE_%=:\n\t"
            "}"
            :: "r"(mbar), "r"(parity) : "memory");
    }
}
__device__ __forceinline__ void cluster_sync_all() {
    asm volatile("barrier.cluster.arrive.aligned;" ::: "memory");
    asm volatile("barrier.cluster.wait.aligned;" ::: "memory");
}

// ---------------------------------------------------------------------------
// Kernel 1: x_proj = sentence @ W_ih + b, f32x2 math, 16 rows per CTA.
// 256 threads: ks = t>>6 (4-way k-split, 64 k), jg = t&63 (4 cols / 2 pairs).
// Dynamic smem: xrep[16][256] ull (32KB, x replicated pairs) +
//               part[4][16][128] ull (64KB).
// ---------------------------------------------------------------------------
__global__ __launch_bounds__(256, 2) void xproj_kernel(
    const float* __restrict__ sent,
    const float* __restrict__ Wih,
    const float* __restrict__ bias)
{
    extern __shared__ ull dsm[];
    ull* xrep = dsm;                 // [16][256]
    ull* part = dsm + 16 * 256;      // [4][16][128]

    const int t  = threadIdx.x;
    const int m0 = blockIdx.x * 16;

    // fill xrep: replicated (x,x) pairs
    #pragma unroll
    for (int it = 0; it < 16; it++) {
        const int idx = t + it * 256;
        const int row = idx >> 8;
        const int k   = idx & 255;
        const float v = sent[(size_t)(m0 + row) * 256 + k];
        xrep[row * 256 + k] = pack2(v, v);
    }
    __syncthreads();

    const int jg = t & 63;
    const int ks = t >> 6;
    const ulonglong2* W2 = (const ulonglong2*)Wih;

    ull a01[16], a23[16];
    #pragma unroll
    for (int r = 0; r < 16; r++) { a01[r] = 0; a23[r] = 0; }

    #pragma unroll 4
    for (int i = 0; i < 64; i++) {
        const int k = ks * 64 + i;
        const ulonglong2 wv = W2[k * 64 + jg];   // cols 4jg..4jg+3
        #pragma unroll
        for (int r = 0; r < 16; r++) {
            const ull xv = xrep[r * 256 + k];    // broadcast
            a01[r] = fma2(wv.x, xv, a01[r]);
            a23[r] = fma2(wv.y, xv, a23[r]);
        }
    }

    #pragma unroll
    for (int r = 0; r < 16; r++) {
        part[(ks * 16 + r) * 128 + 2 * jg]     = a01[r];
        part[(ks * 16 + r) * 128 + 2 * jg + 1] = a23[r];
    }
    __syncthreads();

    const int p  = t & 127;
    const int rb = (t >> 7) * 8;
    const ull bp = *(const ull*)&bias[2 * p];
    #pragma unroll
    for (int rr = 0; rr < 8; rr++) {
        const int r = rb + rr;
        ull v = add2(add2(part[(0 * 16 + r) * 128 + p], part[(1 * 16 + r) * 128 + p]),
                     add2(part[(2 * 16 + r) * 128 + p], part[(3 * 16 + r) * 128 + p]));
        v = add2(v, bp);
        *(ull*)&g_xproj[(size_t)(m0 + r) * 256 + 2 * p] = v;
    }
}

// ---------------------------------------------------------------------------
// Kernel 2: the scan. 2-CTA cluster per batch row (128 CTAs total).
// CTA rank r owns output columns [r*128, r*128+128). W slice (256k x 128cols)
// fully REGISTER-resident: 512 threads, ks=t>>6 (8-way k-split, 32 k),
// jq=t&63 (1 col-pair) -> 32 ull W regs/thread. Zero W traffic per step.
// h double-buffered in SMEM as replicated (h,h) pairs; each step the 64
// reducer threads write the CTA's 128 new h values locally AND to the peer
// CTA via st.async + mbarrier complete_tx (two alternating mbarriers).
// ---------------------------------------------------------------------------
__global__ __launch_bounds__(512, 1) __cluster_dims__(2, 1, 1)
void scan_kernel(
    const float* __restrict__ Whh,    // [256,256] row-major (k, j)
    const float* __restrict__ h0,     // [64,256]
    float* __restrict__ out)          // [64,256]
{
    __shared__ __align__(16) ull hbuf[2][256];   // replicated (h,h) pairs
    __shared__ __align__(16) ull part[8][64];
    __shared__ __align__(8)  ull mbar_store[2];

    const int t    = threadIdx.x;
    const int b    = blockIdx.x >> 1;
    const uint32_t rank  = ctarank();
    const uint32_t prank = rank ^ 1u;
    const int ks    = t >> 6;          // 0..7
    const int jq    = t & 63;          // col-pair within this CTA's half
    const int gc    = (int)rank * 128 + 2 * jq;   // first of 2 global cols
    const int kbase = ks * 32;

    // register-resident W slice: 32 k's x 2 cols
    ull wr[32];
    #pragma unroll
    for (int i = 0; i < 32; i++)
        wr[i] = *(const ull*)&Whh[(size_t)(kbase + i) * 256 + gc];

    // init h buffer 0 (full h, replicated pairs)
    if (t < 256) {
        const float h = h0[(size_t)b * 256 + t];
        hbuf[0][t] = pack2(h, h);
    }
    const uint32_t mb0 = smem_u32(&mbar_store[0]);
    const uint32_t mb1 = smem_u32(&mbar_store[1]);
    if (t == 0) { mbar_init(mb0, 1); mbar_init(mb1, 1); }
    __syncthreads();
    cluster_sync_all();   // peer's mbarriers live before any st.async

    // peer addresses
    const uint32_t peer_hb   = mapa_cluster(smem_u32(&hbuf[0][0]), prank);
    const uint32_t peer_mb0  = mapa_cluster(mb0, prank);
    const uint32_t peer_mb1  = mapa_cluster(mb1, prank);

    // x prefetch (reducers own col-pair gc)
    ull xcur = 0, xnext = 0;
    if (t < 64)
        xcur = *(const ull*)&g_xproj[((size_t)0 * B_SZ + b) * 256 + gc];

    for (int s = 0; s < S_LEN; s++) {
        const int cb = s & 1;
        const int nb = cb ^ 1;
        const uint32_t mbar      = cb ? mb1 : mb0;
        const uint32_t peer_mbar = cb ? peer_mb1 : peer_mb0;
        const uint32_t parity    = (uint32_t)((s >> 1) & 1);

        if (t == 0) mbar_arrive_expect_tx(mbar, 1024);
        if (t < 64) {
            const int sn = (s + 1 < S_LEN) ? s + 1 : s;
            xnext = *(const ull*)&g_xproj[((size_t)sn * B_SZ + b) * 256 + gc];
        }

        const ull* hb = &hbuf[cb][kbase];
        ull a = 0;
        #pragma unroll
        for (int p = 0; p < 16; p++) {
            const ulonglong2 hv = *(const ulonglong2*)(hb + 2 * p);
            a = fma2(wr[2 * p],     hv.x, a);
            a = fma2(wr[2 * p + 1], hv.y, a);
        }
        part[ks][jq] = a;
        __syncthreads();                 // partials visible; hbuf[cb] reads done

        if (t < 64) {
            ull v = add2(add2(add2(part[0][t], part[1][t]),
                              add2(part[2][t], part[3][t])),
                         add2(add2(part[4][t], part[5][t]),
                              add2(part[6][t], part[7][t])));
            v = add2(v, xcur);
            float vx, vy;
            unpack2(v, vx, vy);
            const float tx = tanhf(vx);
            const float ty = tanhf(vy);
            const ull h0p = pack2(tx, tx);
            const ull h1p = pack2(ty, ty);
            hbuf[nb][gc]     = h0p;
            hbuf[nb][gc + 1] = h1p;
            st_async64(peer_hb + (uint32_t)(nb * 256 + gc)     * 8, h0p, peer_mbar);
            st_async64(peer_hb + (uint32_t)(nb * 256 + gc + 1) * 8, h1p, peer_mbar);
            xcur = xnext;
        }
        __syncthreads();                 // local hbuf[nb] writes visible
        mbar_wait_parity_cluster(mbar, parity);  // peer's 128 values arrived
    }

    // final h is in hbuf[0] (S_LEN even). Each CTA writes its own 128 cols.
    if (t < 64) {
        float vx, vy, wx, wy;
        unpack2(hbuf[0][gc],     vx, vy);
        unpack2(hbuf[0][gc + 1], wx, wy);
        out[(size_t)b * 256 + gc]     = vx;
        out[(size_t)b * 256 + gc + 1] = wx;
    }
}

// ---------------------------------------------------------------------------
extern "C" void kernel_launch(void* const* d_in, const int* in_sizes, int n_in,
                              void* d_out, int out_size)
{
    const float* sentence = (const float*)d_in[0];
    const float* h0       = (const float*)d_in[1];
    const float* W_ih     = (const float*)d_in[2];
    const float* W_hh     = (const float*)d_in[3];
    const float* bias     = (const float*)d_in[4];
    float* out = (float*)d_out;

    (void)in_sizes; (void)n_in; (void)out_size;

    const int xp_smem = (16 * 256 + 4 * 16 * 128) * (int)sizeof(ull);  // 96 KB
    cudaFuncSetAttribute(xproj_kernel,
                         cudaFuncAttributeMaxDynamicSharedMemorySize, xp_smem);

    xproj_kernel<<<(S_LEN * B_SZ) / 16, 256, xp_smem>>>(sentence, W_ih, bias);

    scan_kernel<<<2 * B_SZ, 512>>>(W_hh, h0, out);
}

// round 6
// speedup vs baseline: 1.0745x; 1.0745x over previous
#include <cuda_runtime.h>
#include <math.h>
#include <stdint.h>

#define S_LEN 2048
#define B_SZ  64
#define E_SZ  256
#define H_SZ  256

// Scratch for x_proj: [S, B, H] fp32 = 134 MB
__device__ float g_xproj[(size_t)S_LEN * B_SZ * H_SZ];

typedef unsigned long long ull;

// ---- packed f32x2 helpers (Blackwell sm_103a) -------------------------------
__device__ __forceinline__ ull fma2(ull a, ull b, ull c) {
    ull d;
    asm("fma.rn.f32x2 %0, %1, %2, %3;" : "=l"(d) : "l"(a), "l"(b), "l"(c));
    return d;
}
__device__ __forceinline__ ull add2(ull a, ull b) {
    ull d;
    asm("add.rn.f32x2 %0, %1, %2;" : "=l"(d) : "l"(a), "l"(b));
    return d;
}
__device__ __forceinline__ ull pack2(float lo, float hi) {
    ull d;
    asm("mov.b64 %0, {%1, %2};" : "=l"(d) : "f"(lo), "f"(hi));
    return d;
}
__device__ __forceinline__ void unpack2(ull v, float& lo, float& hi) {
    asm("mov.b64 {%0, %1}, %2;" : "=f"(lo), "=f"(hi) : "l"(v));
}

// ---------------------------------------------------------------------------
// Kernel 1: x_proj = sentence @ W_ih + b  (R4 version — measured 393us)
// ---------------------------------------------------------------------------
__global__ __launch_bounds__(256) void xproj_kernel(
    const float* __restrict__ sent,
    const float* __restrict__ Wih,
    const float* __restrict__ bias)
{
    __shared__ float xs[8][256];
    __shared__ float part[4][8][256];

    const int t  = threadIdx.x;
    const int m0 = blockIdx.x * 8;

    {
        const float4* srow = (const float4*)(sent + (size_t)m0 * 256);
        float4* xs4 = (float4*)&xs[0][0];
        #pragma unroll
        for (int i = 0; i < 2; i++)
            xs4[t + i * 256] = srow[t + i * 256];
    }
    __syncthreads();

    const int jg = t & 63;
    const int ks = t >> 6;
    const float4* W4 = (const float4*)Wih;

    float4 acc[8];
    #pragma unroll
    for (int r = 0; r < 8; r++) acc[r] = make_float4(0.f, 0.f, 0.f, 0.f);

    #pragma unroll 8
    for (int i = 0; i < 64; i++) {
        const int k = ks * 64 + i;
        const float4 w = W4[k * 64 + jg];
        #pragma unroll
        for (int r = 0; r < 8; r++) {
            const float xv = xs[r][k];
            acc[r].x += xv * w.x;
            acc[r].y += xv * w.y;
            acc[r].z += xv * w.z;
            acc[r].w += xv * w.w;
        }
    }

    #pragma unroll
    for (int r = 0; r < 8; r++)
        *(float4*)&part[ks][r][4 * jg] = acc[r];
    __syncthreads();

    const float bj = bias[t];
    #pragma unroll
    for (int r = 0; r < 8; r++) {
        const float v = part[0][r][t] + part[1][r][t] +
                        part[2][r][t] + part[3][r][t] + bj;
        g_xproj[(size_t)(m0 + r) * 256 + t] = v;
    }
}

// ---------------------------------------------------------------------------
// Kernel 2: the scan. 64 CTAs (1 batch row each), 256 threads.
// ks = t>>5 (8-way k-split, 32 k's), jq = t&31 (8 cols = 4 ull accumulators).
// Per-thread W slice = 32k x 8cols = 256 floats:
//   K_REG = 24 k's in registers (96 ull = 192 regs)  -> no crossbar cost
//   K_SMEM = 8 k's in SMEM (64 KB total)             -> 512 crossbar cyc/step
// h in SMEM as replicated (h,h) f32x2 pairs; broadcast reads (16 LDS.128/thr).
// Math via fma.rn.f32x2.
// ---------------------------------------------------------------------------
#define K_REG  24
#define K_SMEM 8

__global__ __launch_bounds__(256, 1) void scan_kernel(
    const float* __restrict__ Whh,    // [256,256] row-major (k, j)
    const float* __restrict__ h0,     // [64,256]
    float* __restrict__ out)          // [64,256]
{
    extern __shared__ ull smem[];
    // layout: sW   [8][K_SMEM][32] x 2 ulonglong2   (64 KB)
    //         part [8][128] ull                     (8 KB)
    //         hbuf [256] ull                        (2 KB)
    ulonglong2* sW   = (ulonglong2*)smem;                       // 8*K_SMEM*32*2
    ull*        part = (ull*)(smem + (size_t)8 * K_SMEM * 32 * 2 * 2);
    ull*        hbuf = part + 8 * 128;

    const int t  = threadIdx.x;
    const int b  = blockIdx.x;
    const int ks = t >> 5;          // 0..7
    const int jq = t & 31;          // owns cols 8jq .. 8jq+7
    const int kbase = ks * 32;

    // ---- one-time: register-resident W (24 k's x 8 cols) ----
    ull wr[4 * K_REG];
    #pragma unroll
    for (int i = 0; i < K_REG; i++) {
        const float* wrow = &Whh[(size_t)(kbase + i) * 256 + 8 * jq];
        const ulonglong2 wa = *(const ulonglong2*)(wrow);
        const ulonglong2 wb = *(const ulonglong2*)(wrow + 4);
        wr[4 * i + 0] = wa.x;
        wr[4 * i + 1] = wa.y;
        wr[4 * i + 2] = wb.x;
        wr[4 * i + 3] = wb.y;
    }

    // ---- one-time: SMEM W (8 k's per ks-group) ----
    // 8 groups * K_SMEM * 32 jq * 2 halves = 4096 ulonglong2 entries
    for (int idx = t; idx < 8 * K_SMEM * 32 * 2; idx += 256) {
        const int half = idx & 1;
        const int fjq  = (idx >> 1) & 31;
        const int fm   = (idx >> 6) % K_SMEM;
        const int fks  = idx / (K_SMEM * 32 * 2);
        const int k    = fks * 32 + K_REG + fm;
        sW[idx] = *(const ulonglong2*)&Whh[(size_t)k * 256 + 8 * fjq + 4 * half];
    }

    // ---- init h (replicated pairs) ----
    {
        const float ha = h0[(size_t)b * 256 + t];
        hbuf[t] = pack2(ha, ha);
    }
    __syncthreads();

    // x_proj prefetch: reducer threads t<128 own ull col-pair t
    ull xcur = 0, xnext = 0;
    if (t < 128)
        xcur = *(const ull*)&g_xproj[((size_t)0 * B_SZ + b) * 256 + 2 * t];

    const ull* hb = hbuf + kbase;
    const ulonglong2* sWg = sW + (size_t)(ks * K_SMEM) * 64 + jq * 2;

    for (int s = 0; s < S_LEN; s++) {
        if (t < 128) {
            const int sn = (s + 1 < S_LEN) ? s + 1 : s;
            xnext = *(const ull*)&g_xproj[((size_t)sn * B_SZ + b) * 256 + 2 * t];
        }

        ull a0 = 0, a1 = 0, a2 = 0, a3 = 0;

        // register half: k = kbase + 0 .. kbase + 23
        #pragma unroll
        for (int p = 0; p < K_REG / 2; p++) {
            const ulonglong2 hv = *(const ulonglong2*)(hb + 2 * p);
            a0 = fma2(wr[8 * p + 0], hv.x, a0);
            a1 = fma2(wr[8 * p + 1], hv.x, a1);
            a2 = fma2(wr[8 * p + 2], hv.x, a2);
            a3 = fma2(wr[8 * p + 3], hv.x, a3);
            a0 = fma2(wr[8 * p + 4], hv.y, a0);
            a1 = fma2(wr[8 * p + 5], hv.y, a1);
            a2 = fma2(wr[8 * p + 6], hv.y, a2);
            a3 = fma2(wr[8 * p + 7], hv.y, a3);
        }
        // smem half: k = kbase + 24 .. kbase + 31
        #pragma unroll
        for (int m = 0; m < K_SMEM; m++) {
            const ull hv = hb[K_REG + m];
            const ulonglong2 w0 = sWg[m * 64];
            const ulonglong2 w1 = sWg[m * 64 + 1];
            a0 = fma2(w0.x, hv, a0);
            a1 = fma2(w0.y, hv, a1);
            a2 = fma2(w1.x, hv, a2);
            a3 = fma2(w1.y, hv, a3);
        }

        // partials: ull col-pairs 4jq .. 4jq+3
        part[ks * 128 + 4 * jq + 0] = a0;
        part[ks * 128 + 4 * jq + 1] = a1;
        part[ks * 128 + 4 * jq + 2] = a2;
        part[ks * 128 + 4 * jq + 3] = a3;
        __syncthreads();     // partials visible; all hbuf reads done

        if (t < 128) {
            ull v = add2(add2(add2(part[0 * 128 + t], part[1 * 128 + t]),
                              add2(part[2 * 128 + t], part[3 * 128 + t])),
                         add2(add2(part[4 * 128 + t], part[5 * 128 + t]),
                              add2(part[6 * 128 + t], part[7 * 128 + t])));
            v = add2(v, xcur);
            float vx, vy;
            unpack2(v, vx, vy);
            const float tx = tanhf(vx);
            const float ty = tanhf(vy);
            hbuf[2 * t]     = pack2(tx, tx);
            hbuf[2 * t + 1] = pack2(ty, ty);
            xcur = xnext;
        }
        __syncthreads();     // new h visible
    }

    // final h (replicated pairs) -> out
    {
        float vx, vy;
        unpack2(hbuf[t], vx, vy);
        out[(size_t)b * 256 + t] = vx;
    }
}

// ---------------------------------------------------------------------------
extern "C" void kernel_launch(void* const* d_in, const int* in_sizes, int n_in,
                              void* d_out, int out_size)
{
    const float* sentence = (const float*)d_in[0];
    const float* h0       = (const float*)d_in[1];
    const float* W_ih     = (const float*)d_in[2];
    const float* W_hh     = (const float*)d_in[3];
    const float* bias     = (const float*)d_in[4];
    float* out = (float*)d_out;

    (void)in_sizes; (void)n_in; (void)out_size;

    xproj_kernel<<<(S_LEN * B_SZ) / 8, 256>>>(sentence, W_ih, bias);

    // dynamic smem: sW 64KB + part 8KB + hbuf 2KB
    const int smem_bytes = (8 * K_SMEM * 32 * 2) * 16 + (8 * 128) * 8 + 256 * 8;
    cudaFuncSetAttribute(scan_kernel,
                         cudaFuncAttributeMaxDynamicSharedMemorySize,
                         smem_bytes);
    scan_kernel<<<B_SZ, 256, smem_bytes>>>(W_hh, h0, out);
}